// round 1
// baseline (speedup 1.0000x reference)
#include <cuda_runtime.h>

#define T_ 64
#define B_ 8
#define S_ 512
#define H_ 512

// Scratch (no allocations allowed) — 18 MB total.
__device__ float g_enc[B_*S_*H_];        // tanh(enc + cov*wcov), [B,S,H]
__device__ float g_a1 [T_*B_*H_];        // dec@Wq + bq, rows r=t*B+b
__device__ float g_a2 [B_*S_*H_];        // enc'@Wc, rows b*S+s
__device__ float g_cat[T_*B_*2*H_];      // [c | dec], rows r=t*B+b

__device__ __forceinline__ float ex2f_(float x){ float y; asm("ex2.approx.f32 %0, %1;" : "=f"(y) : "f"(x)); return y; }
__device__ __forceinline__ float rcpf_(float x){ float y; asm("rcp.approx.f32 %0, %1;" : "=f"(y) : "f"(x)); return y; }

// tanh via ex2.approx (rel err ~2^-22) + rcp.approx: ~1e-6 accurate, 2 MUFU.
__device__ __forceinline__ float fast_tanh(float x){
    x = fminf(fmaxf(x, -15.0f), 15.0f);
    float e = ex2f_(x * 2.8853900817779268f);   // e^(2x)
    return (e - 1.0f) * rcpf_(e + 1.0f);
}

// -------- enc' = tanh(enc + cov*wcov), [S,B,H] -> [B,S,H] --------
__global__ void prep_enc_kernel(const float* __restrict__ enc,
                                const float* __restrict__ cov,
                                const float* __restrict__ wcov)
{
    int idx = blockIdx.x * 256 + threadIdx.x;   // over B*S*H
    int h  = idx & (H_-1);
    int bs = idx >> 9;          // H_=512
    int s  = bs & (S_-1);
    int b  = bs >> 9;           // S_=512
    float e = enc[(s*B_ + b)*H_ + h];
    g_enc[idx] = fast_tanh(fmaf(cov[b*S_ + s], wcov[h], e));
}

// -------- dec -> right half of concat buffer --------
__global__ void copy_dec_kernel(const float* __restrict__ dec)
{
    int idx = blockIdx.x * 256 + threadIdx.x;   // over T*B*H
    int h = idx & (H_-1);
    int r = idx >> 9;
    g_cat[r*(2*H_) + H_ + h] = dec[idx];
}

// -------- generic tiled SGEMM: C[M,N] = A[M,K]@B[K,N] (+bias) --------
// BM=BN=64, BK=16, 256 threads, 4x4 per thread. Dims assumed tile-divisible.
template<bool HAS_BIAS>
__global__ __launch_bounds__(256)
void sgemm64(const float* __restrict__ A, const float* __restrict__ B,
             float* __restrict__ C, const float* __restrict__ bias,
             int K, int lda, int ldb, int ldc,
             long sA, long sB, long sC)
{
    A += (long)blockIdx.z * sA;
    B += (long)blockIdx.z * sB;
    C += (long)blockIdx.z * sC;

    __shared__ float As[16][64];
    __shared__ float Bs[16][64];

    const int tid = threadIdx.x;
    const int tx = tid & 15, ty = tid >> 4;
    const int rowBase = blockIdx.y * 64;
    const int colBase = blockIdx.x * 64;
    const int aRow = tid >> 2, aCol = (tid & 3) << 2;
    const int bRow = tid >> 4, bCol = (tid & 15) << 2;

    float acc[4][4];
    #pragma unroll
    for (int i = 0; i < 4; i++)
        #pragma unroll
        for (int j = 0; j < 4; j++) acc[i][j] = 0.0f;

    for (int k0 = 0; k0 < K; k0 += 16) {
        float4 av = *(const float4*)(A + (long)(rowBase + aRow)*lda + k0 + aCol);
        As[aCol+0][aRow] = av.x;
        As[aCol+1][aRow] = av.y;
        As[aCol+2][aRow] = av.z;
        As[aCol+3][aRow] = av.w;
        *(float4*)(&Bs[bRow][bCol]) =
            *(const float4*)(B + (long)(k0 + bRow)*ldb + colBase + bCol);
        __syncthreads();

        #pragma unroll
        for (int k = 0; k < 16; k++) {
            float4 a = *(const float4*)(&As[k][ty << 2]);
            float4 b = *(const float4*)(&Bs[k][tx << 2]);
            acc[0][0] = fmaf(a.x, b.x, acc[0][0]); acc[0][1] = fmaf(a.x, b.y, acc[0][1]);
            acc[0][2] = fmaf(a.x, b.z, acc[0][2]); acc[0][3] = fmaf(a.x, b.w, acc[0][3]);
            acc[1][0] = fmaf(a.y, b.x, acc[1][0]); acc[1][1] = fmaf(a.y, b.y, acc[1][1]);
            acc[1][2] = fmaf(a.y, b.z, acc[1][2]); acc[1][3] = fmaf(a.y, b.w, acc[1][3]);
            acc[2][0] = fmaf(a.z, b.x, acc[2][0]); acc[2][1] = fmaf(a.z, b.y, acc[2][1]);
            acc[2][2] = fmaf(a.z, b.z, acc[2][2]); acc[2][3] = fmaf(a.z, b.w, acc[2][3]);
            acc[3][0] = fmaf(a.w, b.x, acc[3][0]); acc[3][1] = fmaf(a.w, b.y, acc[3][1]);
            acc[3][2] = fmaf(a.w, b.z, acc[3][2]); acc[3][3] = fmaf(a.w, b.w, acc[3][3]);
        }
        __syncthreads();
    }

    float4 bv = make_float4(0.f, 0.f, 0.f, 0.f);
    if (HAS_BIAS) bv = *(const float4*)(bias + colBase + (tx << 2));
    #pragma unroll
    for (int i = 0; i < 4; i++) {
        float4 o;
        o.x = acc[i][0] + bv.x; o.y = acc[i][1] + bv.y;
        o.z = acc[i][2] + bv.z; o.w = acc[i][3] + bv.w;
        *(float4*)(C + (long)(rowBase + (ty << 2) + i)*ldc + colBase + (tx << 2)) = o;
    }
}

// -------- scores + softmax: one block per (t,b) row --------
// scores[s] = sum_h tanh(a1[r,h] + a2[b,s,h]) * v[h]; softmax over s -> align.
__global__ __launch_bounds__(512)
void scores_softmax_kernel(const float* __restrict__ v,
                           float* __restrict__ align_out)
{
    const int r = blockIdx.x;            // r = t*B + b
    const int b = r & (B_-1);
    const int tid = threadIdx.x;
    const int warp = tid >> 5, lane = tid & 31;

    __shared__ float sa1[H_];
    __shared__ float sv[H_];
    __shared__ float ssc[S_];
    __shared__ float sred[17];

    sa1[tid] = g_a1[r*H_ + tid];
    sv[tid]  = v[tid];
    __syncthreads();

    for (int s = warp; s < S_; s += 16) {
        const float* a2row = g_a2 + ((long)b*S_ + s)*H_;
        float acc = 0.0f;
        #pragma unroll
        for (int h = lane*4; h < H_; h += 128) {
            float4 a  = *(const float4*)(sa1 + h);
            float4 x  = *(const float4*)(a2row + h);
            float4 vv = *(const float4*)(sv + h);
            acc = fmaf(fast_tanh(a.x + x.x), vv.x, acc);
            acc = fmaf(fast_tanh(a.y + x.y), vv.y, acc);
            acc = fmaf(fast_tanh(a.z + x.z), vv.z, acc);
            acc = fmaf(fast_tanh(a.w + x.w), vv.w, acc);
        }
        #pragma unroll
        for (int o = 16; o > 0; o >>= 1) acc += __shfl_xor_sync(0xffffffffu, acc, o);
        if (lane == 0) ssc[s] = acc;
    }
    __syncthreads();

    // softmax over S_=512, one thread per s
    float x = ssc[tid];
    float m = x;
    #pragma unroll
    for (int o = 16; o > 0; o >>= 1) m = fmaxf(m, __shfl_xor_sync(0xffffffffu, m, o));
    if (lane == 0) sred[warp] = m;
    __syncthreads();
    if (warp == 0) {
        float mm = (lane < 16) ? sred[lane] : -1e30f;
        #pragma unroll
        for (int o = 8; o > 0; o >>= 1) mm = fmaxf(mm, __shfl_xor_sync(0xffffffffu, mm, o));
        if (lane == 0) sred[16] = mm;
    }
    __syncthreads();
    const float mx = sred[16];
    float e = ex2f_((x - mx) * 1.4426950408889634f);
    float ssum = e;
    #pragma unroll
    for (int o = 16; o > 0; o >>= 1) ssum += __shfl_xor_sync(0xffffffffu, ssum, o);
    __syncthreads();                 // sred[0..15] free again
    if (lane == 0) sred[warp] = ssum;
    __syncthreads();
    if (warp == 0) {
        float t = (lane < 16) ? sred[lane] : 0.0f;
        #pragma unroll
        for (int o = 8; o > 0; o >>= 1) t += __shfl_xor_sync(0xffffffffu, t, o);
        if (lane == 0) sred[16] = t;
    }
    __syncthreads();
    float p = e * rcpf_(sred[16]);
    align_out[(long)r*S_ + tid] = p;
}

extern "C" void kernel_launch(void* const* d_in, const int* in_sizes, int n_in,
                              void* d_out, int out_size)
{
    const float* dec  = (const float*)d_in[0];   // [T,B,H]
    const float* enc  = (const float*)d_in[1];   // [S,B,H]
    const float* cov  = (const float*)d_in[2];   // [B,S]
    const float* Wq   = (const float*)d_in[3];   // [H,H]
    const float* bq   = (const float*)d_in[4];   // [H]
    const float* Wc   = (const float*)d_in[5];   // [H,H]
    const float* v    = (const float*)d_in[6];   // [H]
    const float* Wo   = (const float*)d_in[7];   // [2H,H]
    const float* bo   = (const float*)d_in[8];   // [H]
    const float* wcov = (const float*)d_in[9];   // [H]

    float* attn_h = (float*)d_out;               // [T,B,H]
    float* align  = (float*)d_out + T_*B_*H_;    // [T,B,S]

    float *enc_p, *a1_p, *a2_p, *cat_p;
    cudaGetSymbolAddress((void**)&enc_p, g_enc);
    cudaGetSymbolAddress((void**)&a1_p,  g_a1);
    cudaGetSymbolAddress((void**)&a2_p,  g_a2);
    cudaGetSymbolAddress((void**)&cat_p, g_cat);

    // 1) enc' = tanh(enc + cov*wcov)
    prep_enc_kernel<<<(B_*S_*H_)/256, 256>>>(enc, cov, wcov);

    // 2) a1 = dec@Wq + bq  (M=T*B=512, K=H, N=H); dec is contiguous [T*B, H]
    sgemm64<true><<<dim3(8, 8, 1), 256>>>(dec, Wq, a1_p, bq,
                                          H_, H_, H_, H_, 0, 0, 0);

    // 3) a2 = enc'@Wc  (M=B*S=4096, K=H, N=H)
    sgemm64<false><<<dim3(8, 64, 1), 256>>>(enc_p, Wc, a2_p, nullptr,
                                            H_, H_, H_, H_, 0, 0, 0);

    // 4) scores + softmax -> align (output region)
    scores_softmax_kernel<<<T_*B_, 512>>>(v, align);

    // 5) dec -> right half of concat
    copy_dec_kernel<<<(T_*B_*H_)/256, 256>>>(dec);

    // 6) c = align@enc' per batch b (M=T=64, K=S, N=H), into left half of concat
    //    A row (t) stride = B*S, batch stride = S; C row stride = B*2H, batch stride = 2H
    sgemm64<false><<<dim3(8, 1, B_), 256>>>(align, enc_p, cat_p, nullptr,
                                            S_, B_*S_, H_, B_*2*H_,
                                            (long)S_, (long)S_*H_, (long)2*H_);

    // 7) attn_h = [c|dec]@Wo + bo  (M=512, K=2H=1024, N=H)
    sgemm64<true><<<dim3(8, 8, 1), 256>>>(cat_p, Wo, attn_h, bo,
                                          2*H_, 2*H_, H_, H_, 0, 0, 0);
}

// round 2
// speedup vs baseline: 1.2688x; 1.2688x over previous
#include <cuda_runtime.h>

#define T_ 64
#define B_ 8
#define S_ 512
#define H_ 512

// Scratch (no allocations allowed).
__device__ float g_enc[B_*S_*H_];        // tanh(enc + cov*wcov), [B,S,H]
__device__ float g_a1 [T_*B_*H_];        // dec@Wq + bq, rows r=t*B+b
__device__ float g_a2 [B_*S_*H_];        // enc'@Wc, rows b*S+s
__device__ float g_cat[T_*B_*2*H_];      // [c | dec], rows r=t*B+b

__device__ __forceinline__ float ex2f_(float x){ float y; asm("ex2.approx.f32 %0, %1;" : "=f"(y) : "f"(x)); return y; }
__device__ __forceinline__ float rcpf_(float x){ float y; asm("rcp.approx.f32 %0, %1;" : "=f"(y) : "f"(x)); return y; }
__device__ __forceinline__ float tanhf_hw(float x){ float y; asm("tanh.approx.f32 %0, %1;" : "=f"(y) : "f"(x)); return y; }

// accurate tanh (~1e-6), used where it's free (memory-bound prep kernel)
__device__ __forceinline__ float fast_tanh(float x){
    x = fminf(fmaxf(x, -15.0f), 15.0f);
    float e = ex2f_(x * 2.8853900817779268f);
    return (e - 1.0f) * rcpf_(e + 1.0f);
}

// -------- enc' = tanh(enc + cov*wcov), [S,B,H] -> [B,S,H] --------
__global__ void prep_enc_kernel(const float* __restrict__ enc,
                                const float* __restrict__ cov,
                                const float* __restrict__ wcov)
{
    int idx = blockIdx.x * 256 + threadIdx.x;
    int h  = idx & (H_-1);
    int bs = idx >> 9;
    int s  = bs & (S_-1);
    int b  = bs >> 9;
    float e = enc[(s*B_ + b)*H_ + h];
    g_enc[idx] = fast_tanh(fmaf(cov[b*S_ + s], wcov[h], e));
}

__global__ void copy_dec_kernel(const float* __restrict__ dec)
{
    int idx = blockIdx.x * 256 + threadIdx.x;
    int h = idx & (H_-1);
    int r = idx >> 9;
    g_cat[r*(2*H_) + H_ + h] = dec[idx];
}

// -------- 64x64x16 SGEMM (kept for small GEMMs) --------
template<bool HAS_BIAS>
__global__ __launch_bounds__(256)
void sgemm64(const float* __restrict__ A, const float* __restrict__ B,
             float* __restrict__ C, const float* __restrict__ bias,
             int K, int lda, int ldb, int ldc,
             long sA, long sB, long sC)
{
    A += (long)blockIdx.z * sA;
    B += (long)blockIdx.z * sB;
    C += (long)blockIdx.z * sC;

    __shared__ float As[16][64];
    __shared__ float Bs[16][64];

    const int tid = threadIdx.x;
    const int tx = tid & 15, ty = tid >> 4;
    const int rowBase = blockIdx.y * 64;
    const int colBase = blockIdx.x * 64;
    const int aRow = tid >> 2, aCol = (tid & 3) << 2;
    const int bRow = tid >> 4, bCol = (tid & 15) << 2;

    float acc[4][4];
    #pragma unroll
    for (int i = 0; i < 4; i++)
        #pragma unroll
        for (int j = 0; j < 4; j++) acc[i][j] = 0.0f;

    for (int k0 = 0; k0 < K; k0 += 16) {
        float4 av = *(const float4*)(A + (long)(rowBase + aRow)*lda + k0 + aCol);
        As[aCol+0][aRow] = av.x;
        As[aCol+1][aRow] = av.y;
        As[aCol+2][aRow] = av.z;
        As[aCol+3][aRow] = av.w;
        *(float4*)(&Bs[bRow][bCol]) =
            *(const float4*)(B + (long)(k0 + bRow)*ldb + colBase + bCol);
        __syncthreads();

        #pragma unroll
        for (int k = 0; k < 16; k++) {
            float4 a = *(const float4*)(&As[k][ty << 2]);
            float4 b = *(const float4*)(&Bs[k][tx << 2]);
            acc[0][0] = fmaf(a.x, b.x, acc[0][0]); acc[0][1] = fmaf(a.x, b.y, acc[0][1]);
            acc[0][2] = fmaf(a.x, b.z, acc[0][2]); acc[0][3] = fmaf(a.x, b.w, acc[0][3]);
            acc[1][0] = fmaf(a.y, b.x, acc[1][0]); acc[1][1] = fmaf(a.y, b.y, acc[1][1]);
            acc[1][2] = fmaf(a.y, b.z, acc[1][2]); acc[1][3] = fmaf(a.y, b.w, acc[1][3]);
            acc[2][0] = fmaf(a.z, b.x, acc[2][0]); acc[2][1] = fmaf(a.z, b.y, acc[2][1]);
            acc[2][2] = fmaf(a.z, b.z, acc[2][2]); acc[2][3] = fmaf(a.z, b.w, acc[2][3]);
            acc[3][0] = fmaf(a.w, b.x, acc[3][0]); acc[3][1] = fmaf(a.w, b.y, acc[3][1]);
            acc[3][2] = fmaf(a.w, b.z, acc[3][2]); acc[3][3] = fmaf(a.w, b.w, acc[3][3]);
        }
        __syncthreads();
    }

    float4 bv = make_float4(0.f, 0.f, 0.f, 0.f);
    if (HAS_BIAS) bv = *(const float4*)(bias + colBase + (tx << 2));
    #pragma unroll
    for (int i = 0; i < 4; i++) {
        float4 o;
        o.x = acc[i][0] + bv.x; o.y = acc[i][1] + bv.y;
        o.z = acc[i][2] + bv.z; o.w = acc[i][3] + bv.w;
        *(float4*)(C + (long)(rowBase + (ty << 2) + i)*ldc + colBase + (tx << 2)) = o;
    }
}

// -------- 128x128x8 SGEMM, 8x8 micro, double-buffered (for the big a2 GEMM) --------
__global__ __launch_bounds__(256)
void sgemm128(const float* __restrict__ A, const float* __restrict__ B,
              float* __restrict__ C, int K, int lda, int ldb, int ldc)
{
    __shared__ float As[2][8][128];
    __shared__ float Bs[2][8][128];

    const int tid = threadIdx.x;
    const int tx = tid & 15, ty = tid >> 4;
    const int rowBase = blockIdx.y * 128;
    const int colBase = blockIdx.x * 128;
    const int aRow = tid >> 1,  aCol = (tid & 1) << 2;   // 128 rows x 8 cols
    const int bRow = tid >> 5,  bCol = (tid & 31) << 2;  // 8 rows x 128 cols

    const float* Aptr = A + (long)(rowBase + aRow)*lda + aCol;
    const float* Bptr = B + (long)bRow*ldb + colBase + bCol;

    float acc[8][8];
    #pragma unroll
    for (int i = 0; i < 8; i++)
        #pragma unroll
        for (int j = 0; j < 8; j++) acc[i][j] = 0.0f;

    // prologue: tile 0 -> buffer 0
    {
        float4 av = *(const float4*)(Aptr);
        As[0][aCol+0][aRow] = av.x; As[0][aCol+1][aRow] = av.y;
        As[0][aCol+2][aRow] = av.z; As[0][aCol+3][aRow] = av.w;
        *(float4*)(&Bs[0][bRow][bCol]) = *(const float4*)(Bptr);
    }
    __syncthreads();

    const int KT = K >> 3;
    for (int kt = 0; kt < KT; kt++) {
        const int cur = kt & 1;
        float4 av, bv;
        const bool more = (kt + 1 < KT);
        if (more) {
            av = *(const float4*)(Aptr + (kt+1)*8);
            bv = *(const float4*)(Bptr + (long)(kt+1)*8*ldb);
        }
        #pragma unroll
        for (int k = 0; k < 8; k++) {
            float4 a0 = *(const float4*)(&As[cur][k][ty << 2]);
            float4 a1 = *(const float4*)(&As[cur][k][(ty << 2) + 64]);
            float4 b0 = *(const float4*)(&Bs[cur][k][tx << 2]);
            float4 b1 = *(const float4*)(&Bs[cur][k][(tx << 2) + 64]);
            float ar[8] = {a0.x,a0.y,a0.z,a0.w,a1.x,a1.y,a1.z,a1.w};
            float br[8] = {b0.x,b0.y,b0.z,b0.w,b1.x,b1.y,b1.z,b1.w};
            #pragma unroll
            for (int i = 0; i < 8; i++)
                #pragma unroll
                for (int j = 0; j < 8; j++)
                    acc[i][j] = fmaf(ar[i], br[j], acc[i][j]);
        }
        if (more) {
            const int nxt = cur ^ 1;
            As[nxt][aCol+0][aRow] = av.x; As[nxt][aCol+1][aRow] = av.y;
            As[nxt][aCol+2][aRow] = av.z; As[nxt][aCol+3][aRow] = av.w;
            *(float4*)(&Bs[nxt][bRow][bCol]) = bv;
        }
        __syncthreads();
    }

    #pragma unroll
    for (int ih = 0; ih < 2; ih++) {
        #pragma unroll
        for (int i = 0; i < 4; i++) {
            int r = rowBase + ih*64 + (ty << 2) + i;
            #pragma unroll
            for (int jh = 0; jh < 2; jh++) {
                float4 o;
                o.x = acc[ih*4+i][jh*4+0]; o.y = acc[ih*4+i][jh*4+1];
                o.z = acc[ih*4+i][jh*4+2]; o.w = acc[ih*4+i][jh*4+3];
                *(float4*)(C + (long)r*ldc + colBase + jh*64 + (tx << 2)) = o;
            }
        }
    }
}

// -------- scores + softmax, 4 t-rows per block --------
// grid (16, 8): x = t-group (4 t each), y = b. 512 threads (16 warps).
__global__ __launch_bounds__(512)
void scores_softmax_kernel(const float* __restrict__ v,
                           float* __restrict__ align_out)
{
    const int tg = blockIdx.x;
    const int b  = blockIdx.y;
    const int tid = threadIdx.x;
    const int warp = tid >> 5, lane = tid & 31;

    __shared__ float sa1[4][H_];
    __shared__ float ssc[4][S_];
    __shared__ float sred[17];

    #pragma unroll
    for (int i = 0; i < 4; i++)
        sa1[i][tid] = g_a1[((tg*4 + i)*B_ + b)*H_ + tid];

    // v in registers: lane covers h = lane*4 + 128*k
    float4 v0 = *(const float4*)(v + lane*4);
    float4 v1 = *(const float4*)(v + lane*4 + 128);
    float4 v2 = *(const float4*)(v + lane*4 + 256);
    float4 v3 = *(const float4*)(v + lane*4 + 384);
    __syncthreads();

    for (int s = warp; s < S_; s += 16) {
        const float* a2row = g_a2 + ((long)b*S_ + s)*H_;
        float4 x0 = *(const float4*)(a2row + lane*4);
        float4 x1 = *(const float4*)(a2row + lane*4 + 128);
        float4 x2 = *(const float4*)(a2row + lane*4 + 256);
        float4 x3 = *(const float4*)(a2row + lane*4 + 384);

        #pragma unroll
        for (int i = 0; i < 4; i++) {
            float4 a0 = *(const float4*)(&sa1[i][lane*4]);
            float4 a1 = *(const float4*)(&sa1[i][lane*4 + 128]);
            float4 a2 = *(const float4*)(&sa1[i][lane*4 + 256]);
            float4 a3 = *(const float4*)(&sa1[i][lane*4 + 384]);
            float acc = 0.0f;
            acc = fmaf(tanhf_hw(a0.x + x0.x), v0.x, acc);
            acc = fmaf(tanhf_hw(a0.y + x0.y), v0.y, acc);
            acc = fmaf(tanhf_hw(a0.z + x0.z), v0.z, acc);
            acc = fmaf(tanhf_hw(a0.w + x0.w), v0.w, acc);
            acc = fmaf(tanhf_hw(a1.x + x1.x), v1.x, acc);
            acc = fmaf(tanhf_hw(a1.y + x1.y), v1.y, acc);
            acc = fmaf(tanhf_hw(a1.z + x1.z), v1.z, acc);
            acc = fmaf(tanhf_hw(a1.w + x1.w), v1.w, acc);
            acc = fmaf(tanhf_hw(a2.x + x2.x), v2.x, acc);
            acc = fmaf(tanhf_hw(a2.y + x2.y), v2.y, acc);
            acc = fmaf(tanhf_hw(a2.z + x2.z), v2.z, acc);
            acc = fmaf(tanhf_hw(a2.w + x2.w), v2.w, acc);
            acc = fmaf(tanhf_hw(a3.x + x3.x), v3.x, acc);
            acc = fmaf(tanhf_hw(a3.y + x3.y), v3.y, acc);
            acc = fmaf(tanhf_hw(a3.z + x3.z), v3.z, acc);
            acc = fmaf(tanhf_hw(a3.w + x3.w), v3.w, acc);
            #pragma unroll
            for (int o = 16; o > 0; o >>= 1)
                acc += __shfl_xor_sync(0xffffffffu, acc, o);
            if (lane == 0) ssc[i][s] = acc;
        }
    }
    __syncthreads();

    // softmax over s for each of the 4 rows
    #pragma unroll
    for (int i = 0; i < 4; i++) {
        float x = ssc[i][tid];
        float m = x;
        #pragma unroll
        for (int o = 16; o > 0; o >>= 1) m = fmaxf(m, __shfl_xor_sync(0xffffffffu, m, o));
        if (lane == 0) sred[warp] = m;
        __syncthreads();
        if (warp == 0) {
            float mm = (lane < 16) ? sred[lane] : -1e30f;
            #pragma unroll
            for (int o = 8; o > 0; o >>= 1) mm = fmaxf(mm, __shfl_xor_sync(0xffffffffu, mm, o));
            if (lane == 0) sred[16] = mm;
        }
        __syncthreads();
        const float mx = sred[16];
        float e = ex2f_((x - mx) * 1.4426950408889634f);
        float ssum = e;
        #pragma unroll
        for (int o = 16; o > 0; o >>= 1) ssum += __shfl_xor_sync(0xffffffffu, ssum, o);
        __syncthreads();
        if (lane == 0) sred[warp] = ssum;
        __syncthreads();
        if (warp == 0) {
            float t = (lane < 16) ? sred[lane] : 0.0f;
            #pragma unroll
            for (int o = 8; o > 0; o >>= 1) t += __shfl_xor_sync(0xffffffffu, t, o);
            if (lane == 0) sred[16] = t;
        }
        __syncthreads();
        float p = e * rcpf_(sred[16]);
        align_out[(long)((tg*4 + i)*B_ + b)*S_ + tid] = p;
        __syncthreads();
    }
}

extern "C" void kernel_launch(void* const* d_in, const int* in_sizes, int n_in,
                              void* d_out, int out_size)
{
    const float* dec  = (const float*)d_in[0];
    const float* enc  = (const float*)d_in[1];
    const float* cov  = (const float*)d_in[2];
    const float* Wq   = (const float*)d_in[3];
    const float* bq   = (const float*)d_in[4];
    const float* Wc   = (const float*)d_in[5];
    const float* v    = (const float*)d_in[6];
    const float* Wo   = (const float*)d_in[7];
    const float* bo   = (const float*)d_in[8];
    const float* wcov = (const float*)d_in[9];

    float* attn_h = (float*)d_out;
    float* align  = (float*)d_out + T_*B_*H_;

    float *enc_p, *a1_p, *a2_p, *cat_p;
    cudaGetSymbolAddress((void**)&enc_p, g_enc);
    cudaGetSymbolAddress((void**)&a1_p,  g_a1);
    cudaGetSymbolAddress((void**)&a2_p,  g_a2);
    cudaGetSymbolAddress((void**)&cat_p, g_cat);

    // 1) enc' = tanh(enc + cov*wcov)
    prep_enc_kernel<<<(B_*S_*H_)/256, 256>>>(enc, cov, wcov);

    // 2) a1 = dec@Wq + bq  (M=512, K=512, N=512)
    sgemm64<true><<<dim3(8, 8, 1), 256>>>(dec, Wq, a1_p, bq,
                                          H_, H_, H_, H_, 0, 0, 0);

    // 3) a2 = enc'@Wc  (M=4096, K=512, N=512) — big one, 128x128 tiles
    sgemm128<<<dim3(4, 32), 256>>>(enc_p, Wc, a2_p, H_, H_, H_, H_);

    // 4) scores + softmax -> align
    scores_softmax_kernel<<<dim3(16, 8), 512>>>(v, align);

    // 5) dec -> right half of concat
    copy_dec_kernel<<<(T_*B_*H_)/256, 256>>>(dec);

    // 6) c = align@enc' per batch (M=64, K=512, N=512)
    sgemm64<false><<<dim3(8, 1, B_), 256>>>(align, enc_p, cat_p, nullptr,
                                            S_, B_*S_, H_, B_*2*H_,
                                            (long)S_, (long)S_*H_, (long)2*H_);

    // 7) attn_h = [c|dec]@Wo + bo  (M=512, K=1024, N=512)
    sgemm64<true><<<dim3(8, 8, 1), 256>>>(cat_p, Wo, attn_h, bo,
                                          2*H_, 2*H_, H_, H_, 0, 0, 0);
}

// round 3
// speedup vs baseline: 1.5235x; 1.2007x over previous
#include <cuda_runtime.h>
#include <cstdint>

#define T_ 64
#define B_ 8
#define S_ 512
#define H_ 512

// Scratch (no allocations allowed).
__device__ float g_enc[B_*S_*H_];        // tanh(enc + cov*wcov), [B,S,H]
__device__ float g_a1 [T_*B_*H_];        // dec@Wq + bq, rows r=t*B+b
__device__ float g_a2 [B_*S_*H_];        // enc'@Wc, rows b*S+s
__device__ float g_c  [T_*B_*H_];        // context c, rows r=t*B+b

__device__ __forceinline__ float ex2f_(float x){ float y; asm("ex2.approx.f32 %0, %1;" : "=f"(y) : "f"(x)); return y; }
__device__ __forceinline__ float rcpf_(float x){ float y; asm("rcp.approx.f32 %0, %1;" : "=f"(y) : "f"(x)); return y; }
__device__ __forceinline__ float tanhf_hw(float x){ float y; asm("tanh.approx.f32 %0, %1;" : "=f"(y) : "f"(x)); return y; }

__device__ __forceinline__ float fast_tanh(float x){
    x = fminf(fmaxf(x, -15.0f), 15.0f);
    float e = ex2f_(x * 2.8853900817779268f);
    return (e - 1.0f) * rcpf_(e + 1.0f);
}

// ---- packed f32x2 helpers (Blackwell 2x-width fp32 pipe) ----
__device__ __forceinline__ void ffma2(uint64_t& d, uint64_t a, uint64_t b){
    asm("fma.rn.f32x2 %0, %1, %2, %0;" : "+l"(d) : "l"(a), "l"(b));
}
__device__ __forceinline__ uint64_t pk2dup(float a){
    uint64_t r; asm("mov.b64 %0, {%1, %1};" : "=l"(r) : "f"(a)); return r;
}
__device__ __forceinline__ float2 upk2(uint64_t p){
    float2 f; asm("mov.b64 {%0, %1}, %2;" : "=f"(f.x), "=f"(f.y) : "l"(p)); return f;
}

// -------- enc' = tanh(enc + cov*wcov), [S,B,H] -> [B,S,H] --------
__global__ void prep_enc_kernel(const float* __restrict__ enc,
                                const float* __restrict__ cov,
                                const float* __restrict__ wcov)
{
    int idx = blockIdx.x * 256 + threadIdx.x;
    int h  = idx & (H_-1);
    int bs = idx >> 9;
    int s  = bs & (S_-1);
    int b  = bs >> 9;
    float e = enc[(s*B_ + b)*H_ + h];
    g_enc[idx] = fast_tanh(fmaf(cov[b*S_ + s], wcov[h], e));
}

// -------- combined a1+a2 GEMM: 128x128x8 tiles, f32x2 micro, double-buffered --------
// blocks 0..127: a2 = enc'@Wc (M=4096). blocks 128..143: a1 = dec@Wq + bq (M=512).
__global__ __launch_bounds__(256)
void qc_gemm_kernel(const float* __restrict__ encp, const float* __restrict__ Wc,
                    float* __restrict__ a2out,
                    const float* __restrict__ dec, const float* __restrict__ Wq,
                    const float* __restrict__ bq, float* __restrict__ a1out)
{
    __shared__ float As[2][8][128];
    __shared__ float Bs[2][8][128];

    const float *A, *B, *bias;
    float *C;
    int bx, by;
    {
        int id = blockIdx.x;
        if (id < 128) { A = encp; B = Wc; C = a2out; bias = nullptr; bx = id & 3; by = id >> 2; }
        else          { int j = id - 128; A = dec; B = Wq; C = a1out; bias = bq; bx = j & 3; by = j >> 2; }
    }

    const int tid = threadIdx.x;
    const int tx = tid & 15, ty = tid >> 4;
    const int rowBase = by * 128;
    const int colBase = bx * 128;
    const int aRow = tid >> 1,  aCol = (tid & 1) << 2;
    const int bRow = tid >> 5,  bCol = (tid & 31) << 2;

    const float* Aptr = A + (long)(rowBase + aRow)*H_ + aCol;
    const float* Bptr = B + (long)bRow*H_ + colBase + bCol;

    uint64_t acc[8][4];
    #pragma unroll
    for (int i = 0; i < 8; i++)
        #pragma unroll
        for (int j = 0; j < 4; j++) acc[i][j] = 0ull;

    {
        float4 av = *(const float4*)(Aptr);
        As[0][aCol+0][aRow] = av.x; As[0][aCol+1][aRow] = av.y;
        As[0][aCol+2][aRow] = av.z; As[0][aCol+3][aRow] = av.w;
        *(float4*)(&Bs[0][bRow][bCol]) = *(const float4*)(Bptr);
    }
    __syncthreads();

    const int KT = H_ >> 3;    // 64
    for (int kt = 0; kt < KT; kt++) {
        const int cur = kt & 1;
        float4 av, bv;
        const bool more = (kt + 1 < KT);
        if (more) {
            av = *(const float4*)(Aptr + (kt+1)*8);
            bv = *(const float4*)(Bptr + (long)(kt+1)*8*H_);
        }
        #pragma unroll
        for (int k = 0; k < 8; k++) {
            float4 a0 = *(const float4*)(&As[cur][k][ty << 2]);
            float4 a1 = *(const float4*)(&As[cur][k][(ty << 2) + 64]);
            ulonglong2 bb0 = *(const ulonglong2*)(&Bs[cur][k][tx << 2]);
            ulonglong2 bb1 = *(const ulonglong2*)(&Bs[cur][k][(tx << 2) + 64]);
            uint64_t br[4] = {bb0.x, bb0.y, bb1.x, bb1.y};
            uint64_t pr[8] = {pk2dup(a0.x), pk2dup(a0.y), pk2dup(a0.z), pk2dup(a0.w),
                              pk2dup(a1.x), pk2dup(a1.y), pk2dup(a1.z), pk2dup(a1.w)};
            #pragma unroll
            for (int i = 0; i < 8; i++)
                #pragma unroll
                for (int j = 0; j < 4; j++)
                    ffma2(acc[i][j], pr[i], br[j]);
        }
        if (more) {
            const int nxt = cur ^ 1;
            As[nxt][aCol+0][aRow] = av.x; As[nxt][aCol+1][aRow] = av.y;
            As[nxt][aCol+2][aRow] = av.z; As[nxt][aCol+3][aRow] = av.w;
            *(float4*)(&Bs[nxt][bRow][bCol]) = bv;
        }
        __syncthreads();
    }

    #pragma unroll
    for (int ih = 0; ih < 2; ih++) {
        #pragma unroll
        for (int i = 0; i < 4; i++) {
            int r = rowBase + ih*64 + (ty << 2) + i;
            #pragma unroll
            for (int jh = 0; jh < 2; jh++) {
                float2 p0 = upk2(acc[ih*4+i][jh*2+0]);
                float2 p1 = upk2(acc[ih*4+i][jh*2+1]);
                float4 o = make_float4(p0.x, p0.y, p1.x, p1.y);
                int col = colBase + jh*64 + (tx << 2);
                if (bias) {
                    float4 bvv = *(const float4*)(bias + col);
                    o.x += bvv.x; o.y += bvv.y; o.z += bvv.z; o.w += bvv.w;
                }
                *(float4*)(C + (long)r*H_ + col) = o;
            }
        }
    }
}

// -------- 64x64x16 SGEMM with f32x2, optional bias / dual-A / batch strides --------
template<bool HAS_BIAS, bool DUAL>
__global__ __launch_bounds__(256)
void sgemm64_f2(const float* __restrict__ A, const float* __restrict__ A2,
                const float* __restrict__ B,
                float* __restrict__ C, const float* __restrict__ bias,
                int K, int lda, int ldb, int ldc,
                long sA, long sB, long sC)
{
    A += (long)blockIdx.z * sA;
    B += (long)blockIdx.z * sB;
    C += (long)blockIdx.z * sC;

    __shared__ float As[16][64];
    __shared__ float Bs[16][64];

    const int tid = threadIdx.x;
    const int tx = tid & 15, ty = tid >> 4;
    const int rowBase = blockIdx.y * 64;
    const int colBase = blockIdx.x * 64;
    const int aRow = tid >> 2, aCol = (tid & 3) << 2;
    const int bRow = tid >> 4, bCol = (tid & 15) << 2;

    uint64_t acc[4][2];
    #pragma unroll
    for (int i = 0; i < 4; i++) { acc[i][0] = 0ull; acc[i][1] = 0ull; }

    for (int k0 = 0; k0 < K; k0 += 16) {
        const float* Asrc = A;
        int ka = k0;
        if (DUAL && k0 >= 512) { Asrc = A2; ka = k0 - 512; }
        float4 av = *(const float4*)(Asrc + (long)(rowBase + aRow)*lda + ka + aCol);
        As[aCol+0][aRow] = av.x;
        As[aCol+1][aRow] = av.y;
        As[aCol+2][aRow] = av.z;
        As[aCol+3][aRow] = av.w;
        *(float4*)(&Bs[bRow][bCol]) =
            *(const float4*)(B + (long)(k0 + bRow)*ldb + colBase + bCol);
        __syncthreads();

        #pragma unroll
        for (int k = 0; k < 16; k++) {
            float4 a = *(const float4*)(&As[k][ty << 2]);
            ulonglong2 bb = *(const ulonglong2*)(&Bs[k][tx << 2]);
            uint64_t pr[4] = {pk2dup(a.x), pk2dup(a.y), pk2dup(a.z), pk2dup(a.w)};
            #pragma unroll
            for (int i = 0; i < 4; i++) {
                ffma2(acc[i][0], pr[i], bb.x);
                ffma2(acc[i][1], pr[i], bb.y);
            }
        }
        __syncthreads();
    }

    float4 bv = make_float4(0.f, 0.f, 0.f, 0.f);
    if (HAS_BIAS) bv = *(const float4*)(bias + colBase + (tx << 2));
    #pragma unroll
    for (int i = 0; i < 4; i++) {
        float2 p0 = upk2(acc[i][0]);
        float2 p1 = upk2(acc[i][1]);
        float4 o = make_float4(p0.x + bv.x, p0.y + bv.y, p1.x + bv.z, p1.y + bv.w);
        *(float4*)(C + (long)(rowBase + (ty << 2) + i)*ldc + colBase + (tx << 2)) = o;
    }
}

// -------- scores + softmax, 4 t-rows per block, prefetched s-tiles --------
// grid (16, 8): x = t-group (4 t each), y = b. 512 threads (16 warps).
__global__ __launch_bounds__(512)
void scores_softmax_kernel(const float* __restrict__ v,
                           float* __restrict__ align_out)
{
    const int tg = blockIdx.x;
    const int b  = blockIdx.y;
    const int tid = threadIdx.x;
    const int warp = tid >> 5, lane = tid & 31;

    __shared__ float sa1[4][H_];
    __shared__ float ssc[4][S_];
    __shared__ float sred[17];

    #pragma unroll
    for (int i = 0; i < 4; i++)
        sa1[i][tid] = g_a1[((tg*4 + i)*B_ + b)*H_ + tid];

    float4 v0 = *(const float4*)(v + lane*4);
    float4 v1 = *(const float4*)(v + lane*4 + 128);
    float4 v2 = *(const float4*)(v + lane*4 + 256);
    float4 v3 = *(const float4*)(v + lane*4 + 384);
    __syncthreads();

    const float* a2base = g_a2 + (long)b*S_*H_ + lane*4;

    // prefetch s = warp
    float4 x[4];
    {
        const float* p = a2base + (long)warp*H_;
        x[0] = *(const float4*)(p);
        x[1] = *(const float4*)(p + 128);
        x[2] = *(const float4*)(p + 256);
        x[3] = *(const float4*)(p + 384);
    }

    for (int s = warp; s < S_; s += 16) {
        float4 y[4];
        const int sn = s + 16;
        if (sn < S_) {
            const float* p = a2base + (long)sn*H_;
            y[0] = *(const float4*)(p);
            y[1] = *(const float4*)(p + 128);
            y[2] = *(const float4*)(p + 256);
            y[3] = *(const float4*)(p + 384);
        }

        #pragma unroll
        for (int i = 0; i < 4; i++) {
            float4 a0 = *(const float4*)(&sa1[i][lane*4]);
            float4 a1 = *(const float4*)(&sa1[i][lane*4 + 128]);
            float4 a2 = *(const float4*)(&sa1[i][lane*4 + 256]);
            float4 a3 = *(const float4*)(&sa1[i][lane*4 + 384]);
            float acc = 0.0f;
            acc = fmaf(tanhf_hw(a0.x + x[0].x), v0.x, acc);
            acc = fmaf(tanhf_hw(a0.y + x[0].y), v0.y, acc);
            acc = fmaf(tanhf_hw(a0.z + x[0].z), v0.z, acc);
            acc = fmaf(tanhf_hw(a0.w + x[0].w), v0.w, acc);
            acc = fmaf(tanhf_hw(a1.x + x[1].x), v1.x, acc);
            acc = fmaf(tanhf_hw(a1.y + x[1].y), v1.y, acc);
            acc = fmaf(tanhf_hw(a1.z + x[1].z), v1.z, acc);
            acc = fmaf(tanhf_hw(a1.w + x[1].w), v1.w, acc);
            acc = fmaf(tanhf_hw(a2.x + x[2].x), v2.x, acc);
            acc = fmaf(tanhf_hw(a2.y + x[2].y), v2.y, acc);
            acc = fmaf(tanhf_hw(a2.z + x[2].z), v2.z, acc);
            acc = fmaf(tanhf_hw(a2.w + x[2].w), v2.w, acc);
            acc = fmaf(tanhf_hw(a3.x + x[3].x), v3.x, acc);
            acc = fmaf(tanhf_hw(a3.y + x[3].y), v3.y, acc);
            acc = fmaf(tanhf_hw(a3.z + x[3].z), v3.z, acc);
            acc = fmaf(tanhf_hw(a3.w + x[3].w), v3.w, acc);
            #pragma unroll
            for (int o = 16; o > 0; o >>= 1)
                acc += __shfl_xor_sync(0xffffffffu, acc, o);
            if (lane == 0) ssc[i][s] = acc;
        }
        x[0] = y[0]; x[1] = y[1]; x[2] = y[2]; x[3] = y[3];
    }
    __syncthreads();

    #pragma unroll
    for (int i = 0; i < 4; i++) {
        float xx = ssc[i][tid];
        float m = xx;
        #pragma unroll
        for (int o = 16; o > 0; o >>= 1) m = fmaxf(m, __shfl_xor_sync(0xffffffffu, m, o));
        if (lane == 0) sred[warp] = m;
        __syncthreads();
        if (warp == 0) {
            float mm = (lane < 16) ? sred[lane] : -1e30f;
            #pragma unroll
            for (int o = 8; o > 0; o >>= 1) mm = fmaxf(mm, __shfl_xor_sync(0xffffffffu, mm, o));
            if (lane == 0) sred[16] = mm;
        }
        __syncthreads();
        const float mx = sred[16];
        float e = ex2f_((xx - mx) * 1.4426950408889634f);
        float ssum = e;
        #pragma unroll
        for (int o = 16; o > 0; o >>= 1) ssum += __shfl_xor_sync(0xffffffffu, ssum, o);
        __syncthreads();
        if (lane == 0) sred[warp] = ssum;
        __syncthreads();
        if (warp == 0) {
            float t = (lane < 16) ? sred[lane] : 0.0f;
            #pragma unroll
            for (int o = 8; o > 0; o >>= 1) t += __shfl_xor_sync(0xffffffffu, t, o);
            if (lane == 0) sred[16] = t;
        }
        __syncthreads();
        float p = e * rcpf_(sred[16]);
        align_out[(long)((tg*4 + i)*B_ + b)*S_ + tid] = p;
        __syncthreads();
    }
}

extern "C" void kernel_launch(void* const* d_in, const int* in_sizes, int n_in,
                              void* d_out, int out_size)
{
    const float* dec  = (const float*)d_in[0];
    const float* enc  = (const float*)d_in[1];
    const float* cov  = (const float*)d_in[2];
    const float* Wq   = (const float*)d_in[3];
    const float* bq   = (const float*)d_in[4];
    const float* Wc   = (const float*)d_in[5];
    const float* v    = (const float*)d_in[6];
    const float* Wo   = (const float*)d_in[7];
    const float* bo   = (const float*)d_in[8];
    const float* wcov = (const float*)d_in[9];

    float* attn_h = (float*)d_out;
    float* align  = (float*)d_out + T_*B_*H_;

    float *enc_p, *a1_p, *a2_p, *c_p;
    cudaGetSymbolAddress((void**)&enc_p, g_enc);
    cudaGetSymbolAddress((void**)&a1_p,  g_a1);
    cudaGetSymbolAddress((void**)&a2_p,  g_a2);
    cudaGetSymbolAddress((void**)&c_p,   g_c);

    // 1) enc' = tanh(enc + cov*wcov)
    prep_enc_kernel<<<(B_*S_*H_)/256, 256>>>(enc, cov, wcov);

    // 2+3) a1 = dec@Wq + bq  AND  a2 = enc'@Wc in one 144-block launch
    qc_gemm_kernel<<<144, 256>>>(enc_p, Wc, a2_p, dec, Wq, bq, a1_p);

    // 4) scores + softmax -> align
    scores_softmax_kernel<<<dim3(16, 8), 512>>>(v, align);

    // 5) c = align@enc' per batch (M=64, K=512, N=512) -> g_c rows r=t*B+b
    sgemm64_f2<false, false><<<dim3(8, 1, B_), 256>>>(
        align, nullptr, enc_p, c_p, nullptr,
        S_, B_*S_, H_, B_*H_,
        (long)S_, (long)S_*H_, (long)H_);

    // 6) attn_h = [c|dec]@Wo + bo  (M=512, K=1024 dual-A, N=512)
    sgemm64_f2<true, true><<<dim3(8, 8, 1), 256>>>(
        c_p, dec, Wo, attn_h, bo,
        2*H_, H_, H_, H_, 0, 0, 0);
}

// round 4
// speedup vs baseline: 2.1107x; 1.3854x over previous
#include <cuda_runtime.h>
#include <cstdint>

#define T_ 64
#define B_ 8
#define S_ 512
#define H_ 512
#define TBH (T_*B_*H_)

// Scratch (no allocations allowed).
__device__ float g_enc[B_*S_*H_];        // tanh(enc + cov*wcov), [B,S,H]
__device__ float g_a1 [TBH];             // dec@Wq + bq, rows r=t*B+b
__device__ float g_a2 [B_*S_*H_];        // enc'@Wc, rows b*S+s
__device__ float g_cp [4][TBH];          // c split-K partials
__device__ float g_c  [TBH];             // context c, rows r=t*B+b
__device__ float g_op [4][TBH];          // out split-K partials

__device__ __forceinline__ float ex2f_(float x){ float y; asm("ex2.approx.f32 %0, %1;" : "=f"(y) : "f"(x)); return y; }
__device__ __forceinline__ float rcpf_(float x){ float y; asm("rcp.approx.f32 %0, %1;" : "=f"(y) : "f"(x)); return y; }
__device__ __forceinline__ float tanhf_hw(float x){ float y; asm("tanh.approx.f32 %0, %1;" : "=f"(y) : "f"(x)); return y; }

__device__ __forceinline__ float fast_tanh(float x){
    x = fminf(fmaxf(x, -15.0f), 15.0f);
    float e = ex2f_(x * 2.8853900817779268f);
    return (e - 1.0f) * rcpf_(e + 1.0f);
}

// ---- packed f32x2 helpers ----
__device__ __forceinline__ void ffma2(uint64_t& d, uint64_t a, uint64_t b){
    asm("fma.rn.f32x2 %0, %1, %2, %0;" : "+l"(d) : "l"(a), "l"(b));
}
__device__ __forceinline__ uint64_t pk2dup(float a){
    uint64_t r; asm("mov.b64 %0, {%1, %1};" : "=l"(r) : "f"(a)); return r;
}
__device__ __forceinline__ float2 upk2(uint64_t p){
    float2 f; asm("mov.b64 {%0, %1}, %2;" : "=f"(f.x), "=f"(f.y) : "l"(p)); return f;
}

// -------- enc' = tanh(enc + cov*wcov), [S,B,H] -> [B,S,H] --------
__global__ void prep_enc_kernel(const float* __restrict__ enc,
                                const float* __restrict__ cov,
                                const float* __restrict__ wcov)
{
    int idx = blockIdx.x * 256 + threadIdx.x;
    int h  = idx & (H_-1);
    int bs = idx >> 9;
    int s  = bs & (S_-1);
    int b  = bs >> 9;
    float e = enc[(s*B_ + b)*H_ + h];
    g_enc[idx] = fast_tanh(fmaf(cov[b*S_ + s], wcov[h], e));
}

// -------- combined a1+a2 GEMM: 128x128x8 tiles, f32x2, double-buffered --------
// blocks 0..127: a2 = enc'@Wc (M=4096). blocks 128..143: a1 = dec@Wq + bq (M=512).
__global__ __launch_bounds__(256)
void qc_gemm_kernel(const float* __restrict__ encp, const float* __restrict__ Wc,
                    float* __restrict__ a2out,
                    const float* __restrict__ dec, const float* __restrict__ Wq,
                    const float* __restrict__ bq, float* __restrict__ a1out)
{
    __shared__ float As[2][8][128];
    __shared__ float Bs[2][8][128];

    const float *A, *B, *bias;
    float *C;
    int bx, by;
    {
        int id = blockIdx.x;
        if (id < 128) { A = encp; B = Wc; C = a2out; bias = nullptr; bx = id & 3; by = id >> 2; }
        else          { int j = id - 128; A = dec; B = Wq; C = a1out; bias = bq; bx = j & 3; by = j >> 2; }
    }

    const int tid = threadIdx.x;
    const int tx = tid & 15, ty = tid >> 4;
    const int rowBase = by * 128;
    const int colBase = bx * 128;
    const int aRow = tid >> 1,  aCol = (tid & 1) << 2;
    const int bRow = tid >> 5,  bCol = (tid & 31) << 2;

    const float* Aptr = A + (long)(rowBase + aRow)*H_ + aCol;
    const float* Bptr = B + (long)bRow*H_ + colBase + bCol;

    uint64_t acc[8][4];
    #pragma unroll
    for (int i = 0; i < 8; i++)
        #pragma unroll
        for (int j = 0; j < 4; j++) acc[i][j] = 0ull;

    {
        float4 av = *(const float4*)(Aptr);
        As[0][aCol+0][aRow] = av.x; As[0][aCol+1][aRow] = av.y;
        As[0][aCol+2][aRow] = av.z; As[0][aCol+3][aRow] = av.w;
        *(float4*)(&Bs[0][bRow][bCol]) = *(const float4*)(Bptr);
    }
    __syncthreads();

    const int KT = H_ >> 3;    // 64
    for (int kt = 0; kt < KT; kt++) {
        const int cur = kt & 1;
        float4 av, bv;
        const bool more = (kt + 1 < KT);
        if (more) {
            av = *(const float4*)(Aptr + (kt+1)*8);
            bv = *(const float4*)(Bptr + (long)(kt+1)*8*H_);
        }
        #pragma unroll
        for (int k = 0; k < 8; k++) {
            float4 a0 = *(const float4*)(&As[cur][k][ty << 2]);
            float4 a1 = *(const float4*)(&As[cur][k][(ty << 2) + 64]);
            ulonglong2 bb0 = *(const ulonglong2*)(&Bs[cur][k][tx << 2]);
            ulonglong2 bb1 = *(const ulonglong2*)(&Bs[cur][k][(tx << 2) + 64]);
            uint64_t br[4] = {bb0.x, bb0.y, bb1.x, bb1.y};
            uint64_t pr[8] = {pk2dup(a0.x), pk2dup(a0.y), pk2dup(a0.z), pk2dup(a0.w),
                              pk2dup(a1.x), pk2dup(a1.y), pk2dup(a1.z), pk2dup(a1.w)};
            #pragma unroll
            for (int i = 0; i < 8; i++)
                #pragma unroll
                for (int j = 0; j < 4; j++)
                    ffma2(acc[i][j], pr[i], br[j]);
        }
        if (more) {
            const int nxt = cur ^ 1;
            As[nxt][aCol+0][aRow] = av.x; As[nxt][aCol+1][aRow] = av.y;
            As[nxt][aCol+2][aRow] = av.z; As[nxt][aCol+3][aRow] = av.w;
            *(float4*)(&Bs[nxt][bRow][bCol]) = bv;
        }
        __syncthreads();
    }

    #pragma unroll
    for (int ih = 0; ih < 2; ih++) {
        #pragma unroll
        for (int i = 0; i < 4; i++) {
            int r = rowBase + ih*64 + (ty << 2) + i;
            #pragma unroll
            for (int jh = 0; jh < 2; jh++) {
                float2 p0 = upk2(acc[ih*4+i][jh*2+0]);
                float2 p1 = upk2(acc[ih*4+i][jh*2+1]);
                float4 o = make_float4(p0.x, p0.y, p1.x, p1.y);
                int col = colBase + jh*64 + (tx << 2);
                if (bias) {
                    float4 bvv = *(const float4*)(bias + col);
                    o.x += bvv.x; o.y += bvv.y; o.z += bvv.z; o.w += bvv.w;
                }
                *(float4*)(C + (long)r*H_ + col) = o;
            }
        }
    }
}

// -------- shared 64x64 split-K inner (f32x2) --------
// Computes a 64x64 tile over KCHUNK, A row-stride ldaRow, B row-stride H_.
template<int KCHUNK>
__device__ __forceinline__ void tile64_body(
    const float* __restrict__ A, long ldaRow,   // A points at (row0, k0) of chunk
    const float* __restrict__ Bm,               // Bm points at (k0, col0)
    float* __restrict__ C, long ldcRow)         // C points at (row0, col0)
{
    __shared__ float As[16][64];
    __shared__ float Bs[16][64];

    const int tid = threadIdx.x;
    const int tx = tid & 15, ty = tid >> 4;
    const int aRow = tid >> 2, aCol = (tid & 3) << 2;
    const int bRow = tid >> 4, bCol = (tid & 15) << 2;

    uint64_t acc[4][2];
    #pragma unroll
    for (int i = 0; i < 4; i++) { acc[i][0] = 0ull; acc[i][1] = 0ull; }

    for (int k0 = 0; k0 < KCHUNK; k0 += 16) {
        float4 av = *(const float4*)(A + (long)aRow*ldaRow + k0 + aCol);
        As[aCol+0][aRow] = av.x;
        As[aCol+1][aRow] = av.y;
        As[aCol+2][aRow] = av.z;
        As[aCol+3][aRow] = av.w;
        *(float4*)(&Bs[bRow][bCol]) =
            *(const float4*)(Bm + (long)(k0 + bRow)*H_ + bCol);
        __syncthreads();

        #pragma unroll
        for (int k = 0; k < 16; k++) {
            float4 a = *(const float4*)(&As[k][ty << 2]);
            ulonglong2 bb = *(const ulonglong2*)(&Bs[k][tx << 2]);
            uint64_t pr[4] = {pk2dup(a.x), pk2dup(a.y), pk2dup(a.z), pk2dup(a.w)};
            #pragma unroll
            for (int i = 0; i < 4; i++) {
                ffma2(acc[i][0], pr[i], bb.x);
                ffma2(acc[i][1], pr[i], bb.y);
            }
        }
        __syncthreads();
    }

    #pragma unroll
    for (int i = 0; i < 4; i++) {
        float2 p0 = upk2(acc[i][0]);
        float2 p1 = upk2(acc[i][1]);
        float4 o = make_float4(p0.x, p0.y, p1.x, p1.y);
        *(float4*)(C + (long)((ty << 2) + i)*ldcRow + (tx << 2)) = o;
    }
}

// -------- c partials: grid (8 nTile, 8 b, 4 kz), K=128 per block --------
__global__ __launch_bounds__(256)
void c_splitk_kernel(const float* __restrict__ align)
{
    const int nT = blockIdx.x, b = blockIdx.y, kz = blockIdx.z;
    // A: align[(t*B+b)*S + kz*128 + k], rows t=0..63
    const float* A = align + (long)b*S_ + kz*128;
    // B: enc'[(b*S + kz*128 + k)*H + nT*64 + n]
    const float* Bm = g_enc + ((long)b*S_ + kz*128)*H_ + nT*64;
    // C: g_cp[kz][(t*B+b)*H + nT*64 + n]
    float* C = g_cp[kz] + (long)b*H_ + nT*64;
    tile64_body<128>(A, (long)B_*S_, Bm, C, (long)B_*H_);
}

// -------- c reduce: g_c = sum_kz g_cp[kz] --------
__global__ void c_reduce_kernel()
{
    int idx = (blockIdx.x * 256 + threadIdx.x) * 4;
    float4 a = *(const float4*)(&g_cp[0][idx]);
    float4 b = *(const float4*)(&g_cp[1][idx]);
    float4 c = *(const float4*)(&g_cp[2][idx]);
    float4 d = *(const float4*)(&g_cp[3][idx]);
    float4 o = make_float4(a.x+b.x+c.x+d.x, a.y+b.y+c.y+d.y,
                           a.z+b.z+c.z+d.z, a.w+b.w+c.w+d.w);
    *(float4*)(&g_c[idx]) = o;
}

// -------- out partials: grid (8 nTile, 8 mTile, 4 kz), K=256 per block --------
// kz 0..1: A = g_c (cols kz*256..), kz 2..3: A = dec (cols (kz-2)*256..)
__global__ __launch_bounds__(256)
void out_splitk_kernel(const float* __restrict__ dec, const float* __restrict__ Wo)
{
    const int nT = blockIdx.x, mT = blockIdx.y, kz = blockIdx.z;
    const float* A = (kz < 2) ? (g_c + kz*256) : (dec + (kz-2)*256);
    A += (long)mT*64*H_;
    const float* Bm = Wo + (long)(kz*256)*H_ + nT*64;
    float* C = g_op[kz] + (long)mT*64*H_ + nT*64;
    tile64_body<256>(A, (long)H_, Bm, C, (long)H_);
}

// -------- out reduce + bias --------
__global__ void out_reduce_kernel(float* __restrict__ attn_h,
                                  const float* __restrict__ bo)
{
    int idx = (blockIdx.x * 256 + threadIdx.x) * 4;
    int hq = idx & (H_-1);
    float4 a = *(const float4*)(&g_op[0][idx]);
    float4 b = *(const float4*)(&g_op[1][idx]);
    float4 c = *(const float4*)(&g_op[2][idx]);
    float4 d = *(const float4*)(&g_op[3][idx]);
    float4 bb = *(const float4*)(bo + hq);
    float4 o = make_float4(a.x+b.x+c.x+d.x+bb.x, a.y+b.y+c.y+d.y+bb.y,
                           a.z+b.z+c.z+d.z+bb.z, a.w+b.w+c.w+d.w+bb.w);
    *(float4*)(attn_h + idx) = o;
}

// -------- scores + softmax, 4 t-rows per block, prefetched s-tiles --------
__global__ __launch_bounds__(512)
void scores_softmax_kernel(const float* __restrict__ v,
                           float* __restrict__ align_out)
{
    const int tg = blockIdx.x;
    const int b  = blockIdx.y;
    const int tid = threadIdx.x;
    const int warp = tid >> 5, lane = tid & 31;

    __shared__ float sa1[4][H_];
    __shared__ float ssc[4][S_];
    __shared__ float sred[17];

    #pragma unroll
    for (int i = 0; i < 4; i++)
        sa1[i][tid] = g_a1[((tg*4 + i)*B_ + b)*H_ + tid];

    float4 v0 = *(const float4*)(v + lane*4);
    float4 v1 = *(const float4*)(v + lane*4 + 128);
    float4 v2 = *(const float4*)(v + lane*4 + 256);
    float4 v3 = *(const float4*)(v + lane*4 + 384);
    __syncthreads();

    const float* a2base = g_a2 + (long)b*S_*H_ + lane*4;

    float4 x[4];
    {
        const float* p = a2base + (long)warp*H_;
        x[0] = *(const float4*)(p);
        x[1] = *(const float4*)(p + 128);
        x[2] = *(const float4*)(p + 256);
        x[3] = *(const float4*)(p + 384);
    }

    for (int s = warp; s < S_; s += 16) {
        float4 y[4];
        const int sn = s + 16;
        if (sn < S_) {
            const float* p = a2base + (long)sn*H_;
            y[0] = *(const float4*)(p);
            y[1] = *(const float4*)(p + 128);
            y[2] = *(const float4*)(p + 256);
            y[3] = *(const float4*)(p + 384);
        }

        #pragma unroll
        for (int i = 0; i < 4; i++) {
            float4 a0 = *(const float4*)(&sa1[i][lane*4]);
            float4 a1 = *(const float4*)(&sa1[i][lane*4 + 128]);
            float4 a2 = *(const float4*)(&sa1[i][lane*4 + 256]);
            float4 a3 = *(const float4*)(&sa1[i][lane*4 + 384]);
            float acc = 0.0f;
            acc = fmaf(tanhf_hw(a0.x + x[0].x), v0.x, acc);
            acc = fmaf(tanhf_hw(a0.y + x[0].y), v0.y, acc);
            acc = fmaf(tanhf_hw(a0.z + x[0].z), v0.z, acc);
            acc = fmaf(tanhf_hw(a0.w + x[0].w), v0.w, acc);
            acc = fmaf(tanhf_hw(a1.x + x[1].x), v1.x, acc);
            acc = fmaf(tanhf_hw(a1.y + x[1].y), v1.y, acc);
            acc = fmaf(tanhf_hw(a1.z + x[1].z), v1.z, acc);
            acc = fmaf(tanhf_hw(a1.w + x[1].w), v1.w, acc);
            acc = fmaf(tanhf_hw(a2.x + x[2].x), v2.x, acc);
            acc = fmaf(tanhf_hw(a2.y + x[2].y), v2.y, acc);
            acc = fmaf(tanhf_hw(a2.z + x[2].z), v2.z, acc);
            acc = fmaf(tanhf_hw(a2.w + x[2].w), v2.w, acc);
            acc = fmaf(tanhf_hw(a3.x + x[3].x), v3.x, acc);
            acc = fmaf(tanhf_hw(a3.y + x[3].y), v3.y, acc);
            acc = fmaf(tanhf_hw(a3.z + x[3].z), v3.z, acc);
            acc = fmaf(tanhf_hw(a3.w + x[3].w), v3.w, acc);
            #pragma unroll
            for (int o = 16; o > 0; o >>= 1)
                acc += __shfl_xor_sync(0xffffffffu, acc, o);
            if (lane == 0) ssc[i][s] = acc;
        }
        x[0] = y[0]; x[1] = y[1]; x[2] = y[2]; x[3] = y[3];
    }
    __syncthreads();

    #pragma unroll
    for (int i = 0; i < 4; i++) {
        float xx = ssc[i][tid];
        float m = xx;
        #pragma unroll
        for (int o = 16; o > 0; o >>= 1) m = fmaxf(m, __shfl_xor_sync(0xffffffffu, m, o));
        if (lane == 0) sred[warp] = m;
        __syncthreads();
        if (warp == 0) {
            float mm = (lane < 16) ? sred[lane] : -1e30f;
            #pragma unroll
            for (int o = 8; o > 0; o >>= 1) mm = fmaxf(mm, __shfl_xor_sync(0xffffffffu, mm, o));
            if (lane == 0) sred[16] = mm;
        }
        __syncthreads();
        const float mx = sred[16];
        float e = ex2f_((xx - mx) * 1.4426950408889634f);
        float ssum = e;
        #pragma unroll
        for (int o = 16; o > 0; o >>= 1) ssum += __shfl_xor_sync(0xffffffffu, ssum, o);
        __syncthreads();
        if (lane == 0) sred[warp] = ssum;
        __syncthreads();
        if (warp == 0) {
            float t = (lane < 16) ? sred[lane] : 0.0f;
            #pragma unroll
            for (int o = 8; o > 0; o >>= 1) t += __shfl_xor_sync(0xffffffffu, t, o);
            if (lane == 0) sred[16] = t;
        }
        __syncthreads();
        float p = e * rcpf_(sred[16]);
        align_out[(long)((tg*4 + i)*B_ + b)*S_ + tid] = p;
        __syncthreads();
    }
}

extern "C" void kernel_launch(void* const* d_in, const int* in_sizes, int n_in,
                              void* d_out, int out_size)
{
    const float* dec  = (const float*)d_in[0];
    const float* enc  = (const float*)d_in[1];
    const float* cov  = (const float*)d_in[2];
    const float* Wq   = (const float*)d_in[3];
    const float* bq   = (const float*)d_in[4];
    const float* Wc   = (const float*)d_in[5];
    const float* v    = (const float*)d_in[6];
    const float* Wo   = (const float*)d_in[7];
    const float* bo   = (const float*)d_in[8];
    const float* wcov = (const float*)d_in[9];

    float* attn_h = (float*)d_out;
    float* align  = (float*)d_out + TBH;

    float *enc_p, *a1_p, *a2_p;
    cudaGetSymbolAddress((void**)&enc_p, g_enc);
    cudaGetSymbolAddress((void**)&a1_p,  g_a1);
    cudaGetSymbolAddress((void**)&a2_p,  g_a2);

    // 1) enc' = tanh(enc + cov*wcov)
    prep_enc_kernel<<<(B_*S_*H_)/256, 256>>>(enc, cov, wcov);

    // 2) a1 = dec@Wq + bq AND a2 = enc'@Wc in one 144-block launch
    qc_gemm_kernel<<<144, 256>>>(enc_p, Wc, a2_p, dec, Wq, bq, a1_p);

    // 3) scores + softmax -> align
    scores_softmax_kernel<<<dim3(16, 8), 512>>>(v, align);

    // 4) c partials (256 blocks) + reduce
    c_splitk_kernel<<<dim3(8, 8, 4), 256>>>(align);
    c_reduce_kernel<<<TBH/1024, 256>>>();

    // 5) out partials (256 blocks) + reduce (adds bias)
    out_splitk_kernel<<<dim3(8, 8, 4), 256>>>(dec, Wo);
    out_reduce_kernel<<<TBH/1024, 256>>>(attn_h, bo);
}

// round 6
// speedup vs baseline: 2.1563x; 1.0216x over previous
#include <cuda_runtime.h>
#include <cstdint>

#define T_ 64
#define B_ 8
#define S_ 512
#define H_ 512
#define TBH (T_*B_*H_)
#define BSH (B_*S_*H_)

// Scratch (no device allocations allowed).
__device__ float g_enc[BSH];             // tanh(enc + cov*wcov), [B,S,H]
__device__ float g_a1 [TBH];             // dec@Wq + bq, rows r=t*B+b
__device__ float g_a2 [BSH];             // enc'@Wc, rows b*S+s
__device__ float g_cp [4][TBH];          // c split-K partials
__device__ float g_op [4][TBH];          // out split-K partials

__device__ __forceinline__ float ex2f_(float x){ float y; asm("ex2.approx.f32 %0, %1;" : "=f"(y) : "f"(x)); return y; }
__device__ __forceinline__ float rcpf_(float x){ float y; asm("rcp.approx.f32 %0, %1;" : "=f"(y) : "f"(x)); return y; }
__device__ __forceinline__ float tanhf_hw(float x){ float y; asm("tanh.approx.f32 %0, %1;" : "=f"(y) : "f"(x)); return y; }

__device__ __forceinline__ float fast_tanh(float x){
    x = fminf(fmaxf(x, -15.0f), 15.0f);
    float e = ex2f_(x * 2.8853900817779268f);
    return (e - 1.0f) * rcpf_(e + 1.0f);
}

// ---- packed f32x2 helpers ----
__device__ __forceinline__ void ffma2(uint64_t& d, uint64_t a, uint64_t b){
    asm("fma.rn.f32x2 %0, %1, %2, %0;" : "+l"(d) : "l"(a), "l"(b));
}
__device__ __forceinline__ uint64_t pk2dup(float a){
    uint64_t r; asm("mov.b64 %0, {%1, %1};" : "=l"(r) : "f"(a)); return r;
}
__device__ __forceinline__ float2 upk2(uint64_t p){
    float2 f; asm("mov.b64 {%0, %1}, %2;" : "=f"(f.x), "=f"(f.y) : "l"(p)); return f;
}

// -------- enc' = tanh(enc + cov*wcov), [S,B,H] -> [B,S,H] --------
__global__ void prep_enc_kernel(const float* __restrict__ enc,
                                const float* __restrict__ cov,
                                const float* __restrict__ wcov)
{
    int idx = blockIdx.x * 256 + threadIdx.x;
    int h  = idx & (H_-1);
    int bs = idx >> 9;
    int s  = bs & (S_-1);
    int b  = bs >> 9;
    float e = enc[(s*B_ + b)*H_ + h];
    g_enc[idx] = fast_tanh(fmaf(cov[b*S_ + s], wcov[h], e));
}

// -------- combined a1+a2 GEMM: 128x128x8 tiles, f32x2, double-buffered --------
__global__ __launch_bounds__(256)
void qc_gemm_kernel(const float* __restrict__ encp, const float* __restrict__ Wc,
                    float* __restrict__ a2out,
                    const float* __restrict__ dec, const float* __restrict__ Wq,
                    const float* __restrict__ bq, float* __restrict__ a1out)
{
    __shared__ float As[2][8][128];
    __shared__ float Bs[2][8][128];

    const float *A, *B, *bias;
    float *C;
    int bx, by;
    {
        int id = blockIdx.x;
        if (id < 128) { A = encp; B = Wc; C = a2out; bias = nullptr; bx = id & 3; by = id >> 2; }
        else          { int j = id - 128; A = dec; B = Wq; C = a1out; bias = bq; bx = j & 3; by = j >> 2; }
    }

    const int tid = threadIdx.x;
    const int tx = tid & 15, ty = tid >> 4;
    const int rowBase = by * 128;
    const int colBase = bx * 128;
    const int aRow = tid >> 1,  aCol = (tid & 1) << 2;
    const int bRow = tid >> 5,  bCol = (tid & 31) << 2;

    const float* Aptr = A + (long)(rowBase + aRow)*H_ + aCol;
    const float* Bptr = B + (long)bRow*H_ + colBase + bCol;

    uint64_t acc[8][4];
    #pragma unroll
    for (int i = 0; i < 8; i++)
        #pragma unroll
        for (int j = 0; j < 4; j++) acc[i][j] = 0ull;

    {
        float4 av = *(const float4*)(Aptr);
        As[0][aCol+0][aRow] = av.x; As[0][aCol+1][aRow] = av.y;
        As[0][aCol+2][aRow] = av.z; As[0][aCol+3][aRow] = av.w;
        *(float4*)(&Bs[0][bRow][bCol]) = *(const float4*)(Bptr);
    }
    __syncthreads();

    const int KT = H_ >> 3;    // 64
    for (int kt = 0; kt < KT; kt++) {
        const int cur = kt & 1;
        float4 av, bv;
        const bool more = (kt + 1 < KT);
        if (more) {
            av = *(const float4*)(Aptr + (kt+1)*8);
            bv = *(const float4*)(Bptr + (long)(kt+1)*8*H_);
        }
        #pragma unroll
        for (int k = 0; k < 8; k++) {
            float4 a0 = *(const float4*)(&As[cur][k][ty << 2]);
            float4 a1 = *(const float4*)(&As[cur][k][(ty << 2) + 64]);
            ulonglong2 bb0 = *(const ulonglong2*)(&Bs[cur][k][tx << 2]);
            ulonglong2 bb1 = *(const ulonglong2*)(&Bs[cur][k][(tx << 2) + 64]);
            uint64_t br[4] = {bb0.x, bb0.y, bb1.x, bb1.y};
            uint64_t pr[8] = {pk2dup(a0.x), pk2dup(a0.y), pk2dup(a0.z), pk2dup(a0.w),
                              pk2dup(a1.x), pk2dup(a1.y), pk2dup(a1.z), pk2dup(a1.w)};
            #pragma unroll
            for (int i = 0; i < 8; i++)
                #pragma unroll
                for (int j = 0; j < 4; j++)
                    ffma2(acc[i][j], pr[i], br[j]);
        }
        if (more) {
            const int nxt = cur ^ 1;
            As[nxt][aCol+0][aRow] = av.x; As[nxt][aCol+1][aRow] = av.y;
            As[nxt][aCol+2][aRow] = av.z; As[nxt][aCol+3][aRow] = av.w;
            *(float4*)(&Bs[nxt][bRow][bCol]) = bv;
        }
        __syncthreads();
    }

    #pragma unroll
    for (int ih = 0; ih < 2; ih++) {
        #pragma unroll
        for (int i = 0; i < 4; i++) {
            int r = rowBase + ih*64 + (ty << 2) + i;
            #pragma unroll
            for (int jh = 0; jh < 2; jh++) {
                float2 p0 = upk2(acc[ih*4+i][jh*2+0]);
                float2 p1 = upk2(acc[ih*4+i][jh*2+1]);
                float4 o = make_float4(p0.x, p0.y, p1.x, p1.y);
                int col = colBase + jh*64 + (tx << 2);
                if (bias) {
                    float4 bvv = *(const float4*)(bias + col);
                    o.x += bvv.x; o.y += bvv.y; o.z += bvv.z; o.w += bvv.w;
                }
                *(float4*)(C + (long)r*H_ + col) = o;
            }
        }
    }
}

// -------- 64x64 split-K tile, double-buffered, f32x2 --------
// SUMC: A-load sums 4 consecutive planes of g_cp (stride TBH) — folds c-reduce.
template<int KCHUNK, bool SUMC>
__device__ __forceinline__ void tile64_body(
    const float* __restrict__ A, long ldaRow,
    const float* __restrict__ Bm,
    float* __restrict__ C, long ldcRow)
{
    __shared__ float As[2][16][64];
    __shared__ float Bs[2][16][64];

    const int tid = threadIdx.x;
    const int tx = tid & 15, ty = tid >> 4;
    const int aRow = tid >> 2, aCol = (tid & 3) << 2;
    const int bRow = tid >> 4, bCol = (tid & 15) << 2;

    uint64_t acc[4][2];
    #pragma unroll
    for (int i = 0; i < 4; i++) { acc[i][0] = 0ull; acc[i][1] = 0ull; }

    auto loadA = [&](int k0) -> float4 {
        const float* p = A + (long)aRow*ldaRow + k0 + aCol;
        float4 v = *(const float4*)p;
        if (SUMC) {
            float4 v1 = *(const float4*)(p + (long)TBH);
            float4 v2 = *(const float4*)(p + 2*(long)TBH);
            float4 v3 = *(const float4*)(p + 3*(long)TBH);
            v.x += v1.x + v2.x + v3.x; v.y += v1.y + v2.y + v3.y;
            v.z += v1.z + v2.z + v3.z; v.w += v1.w + v2.w + v3.w;
        }
        return v;
    };

    float4 av = loadA(0);
    float4 bv = *(const float4*)(Bm + (long)bRow*H_ + bCol);
    int buf = 0;

    for (int k0 = 0; k0 < KCHUNK; k0 += 16) {
        As[buf][aCol+0][aRow] = av.x;
        As[buf][aCol+1][aRow] = av.y;
        As[buf][aCol+2][aRow] = av.z;
        As[buf][aCol+3][aRow] = av.w;
        *(float4*)(&Bs[buf][bRow][bCol]) = bv;
        __syncthreads();

        if (k0 + 16 < KCHUNK) {
            av = loadA(k0 + 16);
            bv = *(const float4*)(Bm + (long)(k0 + 16 + bRow)*H_ + bCol);
        }

        #pragma unroll
        for (int k = 0; k < 16; k++) {
            float4 a = *(const float4*)(&As[buf][k][ty << 2]);
            ulonglong2 bb = *(const ulonglong2*)(&Bs[buf][k][tx << 2]);
            uint64_t pr[4] = {pk2dup(a.x), pk2dup(a.y), pk2dup(a.z), pk2dup(a.w)};
            #pragma unroll
            for (int i = 0; i < 4; i++) {
                ffma2(acc[i][0], pr[i], bb.x);
                ffma2(acc[i][1], pr[i], bb.y);
            }
        }
        __syncthreads();
        buf ^= 1;
    }

    #pragma unroll
    for (int i = 0; i < 4; i++) {
        float2 p0 = upk2(acc[i][0]);
        float2 p1 = upk2(acc[i][1]);
        float4 o = make_float4(p0.x, p0.y, p1.x, p1.y);
        *(float4*)(C + (long)((ty << 2) + i)*ldcRow + (tx << 2)) = o;
    }
}

// c partials: grid (8 nT, 8 b, 4 kz), K=128 each
__global__ __launch_bounds__(256)
void c_splitk_kernel(const float* __restrict__ align)
{
    const int nT = blockIdx.x, b = blockIdx.y, kz = blockIdx.z;
    const float* A  = align + (long)b*S_ + kz*128;
    const float* Bm = g_enc + ((long)b*S_ + kz*128)*H_ + nT*64;
    float* C = g_cp[kz] + (long)b*H_ + nT*64;
    tile64_body<128, false>(A, (long)B_*S_, Bm, C, (long)B_*H_);
}

// out partials, c-half (kz 0..1): A = on-the-fly sum of 4 c-partials
__global__ __launch_bounds__(256)
void out_splitk_c_kernel(const float* __restrict__ Wo)
{
    const int nT = blockIdx.x, mT = blockIdx.y, kz = blockIdx.z;   // kz in {0,1}
    const float* A  = g_cp[0] + kz*256 + (long)mT*64*H_;
    const float* Bm = Wo + (long)(kz*256)*H_ + nT*64;
    float* C = g_op[kz] + (long)mT*64*H_ + nT*64;
    tile64_body<256, true>(A, (long)H_, Bm, C, (long)H_);
}

// out partials, dec-half (kz 2..3): depends only on inputs -> runs on side stream
__global__ __launch_bounds__(256)
void out_splitk_d_kernel(const float* __restrict__ dec, const float* __restrict__ Wo)
{
    const int nT = blockIdx.x, mT = blockIdx.y, kz = blockIdx.z + 2;
    const float* A  = dec + (kz-2)*256 + (long)mT*64*H_;
    const float* Bm = Wo + (long)(kz*256)*H_ + nT*64;
    float* C = g_op[kz] + (long)mT*64*H_ + nT*64;
    tile64_body<256, false>(A, (long)H_, Bm, C, (long)H_);
}

__global__ void out_reduce_kernel(float* __restrict__ attn_h,
                                  const float* __restrict__ bo)
{
    int idx = (blockIdx.x * 256 + threadIdx.x) * 4;
    int hq = idx & (H_-1);
    float4 a = *(const float4*)(&g_op[0][idx]);
    float4 b = *(const float4*)(&g_op[1][idx]);
    float4 c = *(const float4*)(&g_op[2][idx]);
    float4 d = *(const float4*)(&g_op[3][idx]);
    float4 bb = *(const float4*)(bo + hq);
    float4 o = make_float4(a.x+b.x+c.x+d.x+bb.x, a.y+b.y+c.y+d.y+bb.y,
                           a.z+b.z+c.z+d.z+bb.z, a.w+b.w+c.w+d.w+bb.w);
    *(float4*)(attn_h + idx) = o;
}

// -------- scores + softmax, 4 t-rows per block, prefetched s-tiles --------
__global__ __launch_bounds__(512)
void scores_softmax_kernel(const float* __restrict__ v,
                           float* __restrict__ align_out)
{
    const int tg = blockIdx.x;
    const int b  = blockIdx.y;
    const int tid = threadIdx.x;
    const int warp = tid >> 5, lane = tid & 31;

    __shared__ float sa1[4][H_];
    __shared__ float ssc[4][S_];
    __shared__ float sred[17];

    #pragma unroll
    for (int i = 0; i < 4; i++)
        sa1[i][tid] = g_a1[((tg*4 + i)*B_ + b)*H_ + tid];

    float4 v0 = *(const float4*)(v + lane*4);
    float4 v1 = *(const float4*)(v + lane*4 + 128);
    float4 v2 = *(const float4*)(v + lane*4 + 256);
    float4 v3 = *(const float4*)(v + lane*4 + 384);
    __syncthreads();

    const float* a2base = g_a2 + (long)b*S_*H_ + lane*4;

    float4 x[4];
    {
        const float* p = a2base + (long)warp*H_;
        x[0] = *(const float4*)(p);
        x[1] = *(const float4*)(p + 128);
        x[2] = *(const float4*)(p + 256);
        x[3] = *(const float4*)(p + 384);
    }

    for (int s = warp; s < S_; s += 16) {
        float4 y[4];
        const int sn = s + 16;
        if (sn < S_) {
            const float* p = a2base + (long)sn*H_;
            y[0] = *(const float4*)(p);
            y[1] = *(const float4*)(p + 128);
            y[2] = *(const float4*)(p + 256);
            y[3] = *(const float4*)(p + 384);
        }

        #pragma unroll
        for (int i = 0; i < 4; i++) {
            float4 a0 = *(const float4*)(&sa1[i][lane*4]);
            float4 a1 = *(const float4*)(&sa1[i][lane*4 + 128]);
            float4 a2 = *(const float4*)(&sa1[i][lane*4 + 256]);
            float4 a3 = *(const float4*)(&sa1[i][lane*4 + 384]);
            float acc = 0.0f;
            acc = fmaf(tanhf_hw(a0.x + x[0].x), v0.x, acc);
            acc = fmaf(tanhf_hw(a0.y + x[0].y), v0.y, acc);
            acc = fmaf(tanhf_hw(a0.z + x[0].z), v0.z, acc);
            acc = fmaf(tanhf_hw(a0.w + x[0].w), v0.w, acc);
            acc = fmaf(tanhf_hw(a1.x + x[1].x), v1.x, acc);
            acc = fmaf(tanhf_hw(a1.y + x[1].y), v1.y, acc);
            acc = fmaf(tanhf_hw(a1.z + x[1].z), v1.z, acc);
            acc = fmaf(tanhf_hw(a1.w + x[1].w), v1.w, acc);
            acc = fmaf(tanhf_hw(a2.x + x[2].x), v2.x, acc);
            acc = fmaf(tanhf_hw(a2.y + x[2].y), v2.y, acc);
            acc = fmaf(tanhf_hw(a2.z + x[2].z), v2.z, acc);
            acc = fmaf(tanhf_hw(a2.w + x[2].w), v2.w, acc);
            acc = fmaf(tanhf_hw(a3.x + x[3].x), v3.x, acc);
            acc = fmaf(tanhf_hw(a3.y + x[3].y), v3.y, acc);
            acc = fmaf(tanhf_hw(a3.z + x[3].z), v3.z, acc);
            acc = fmaf(tanhf_hw(a3.w + x[3].w), v3.w, acc);
            #pragma unroll
            for (int o = 16; o > 0; o >>= 1)
                acc += __shfl_xor_sync(0xffffffffu, acc, o);
            if (lane == 0) ssc[i][s] = acc;
        }
        x[0] = y[0]; x[1] = y[1]; x[2] = y[2]; x[3] = y[3];
    }
    __syncthreads();

    #pragma unroll
    for (int i = 0; i < 4; i++) {
        float xx = ssc[i][tid];
        float m = xx;
        #pragma unroll
        for (int o = 16; o > 0; o >>= 1) m = fmaxf(m, __shfl_xor_sync(0xffffffffu, m, o));
        if (lane == 0) sred[warp] = m;
        __syncthreads();
        if (warp == 0) {
            float mm = (lane < 16) ? sred[lane] : -1e30f;
            #pragma unroll
            for (int o = 8; o > 0; o >>= 1) mm = fmaxf(mm, __shfl_xor_sync(0xffffffffu, mm, o));
            if (lane == 0) sred[16] = mm;
        }
        __syncthreads();
        const float mx = sred[16];
        float e = ex2f_((xx - mx) * 1.4426950408889634f);
        float ssum = e;
        #pragma unroll
        for (int o = 16; o > 0; o >>= 1) ssum += __shfl_xor_sync(0xffffffffu, ssum, o);
        __syncthreads();
        if (lane == 0) sred[warp] = ssum;
        __syncthreads();
        if (warp == 0) {
            float t = (lane < 16) ? sred[lane] : 0.0f;
            #pragma unroll
            for (int o = 8; o > 0; o >>= 1) t += __shfl_xor_sync(0xffffffffu, t, o);
            if (lane == 0) sred[16] = t;
        }
        __syncthreads();
        float p = e * rcpf_(sred[16]);
        align_out[(long)((tg*4 + i)*B_ + b)*S_ + tid] = p;
        __syncthreads();
    }
}

extern "C" void kernel_launch(void* const* d_in, const int* in_sizes, int n_in,
                              void* d_out, int out_size)
{
    const float* dec  = (const float*)d_in[0];
    const float* enc  = (const float*)d_in[1];
    const float* cov  = (const float*)d_in[2];
    const float* Wq   = (const float*)d_in[3];
    const float* bq   = (const float*)d_in[4];
    const float* Wc   = (const float*)d_in[5];
    const float* v    = (const float*)d_in[6];
    const float* Wo   = (const float*)d_in[7];
    const float* bo   = (const float*)d_in[8];
    const float* wcov = (const float*)d_in[9];

    float* attn_h = (float*)d_out;
    float* align  = (float*)d_out + TBH;

    float *enc_p, *a1_p, *a2_p;
    cudaGetSymbolAddress((void**)&enc_p, g_enc);
    cudaGetSymbolAddress((void**)&a1_p,  g_a1);
    cudaGetSymbolAddress((void**)&a2_p,  g_a2);

    // One-time host-side resources (created on the uncaptured correctness call).
    static cudaStream_t s1 = nullptr;
    static cudaEvent_t evFork = nullptr, evJoin = nullptr;
    if (!s1) {
        cudaStreamCreateWithFlags(&s1, cudaStreamNonBlocking);
        cudaEventCreateWithFlags(&evFork, cudaEventDisableTiming);
        cudaEventCreateWithFlags(&evJoin, cudaEventDisableTiming);
    }

    // Fork: out_splitk_d depends only on inputs -> side stream, overlaps main chain.
    cudaEventRecord(evFork, 0);
    cudaStreamWaitEvent(s1, evFork, 0);
    out_splitk_d_kernel<<<dim3(8, 8, 2), 256, 0, s1>>>(dec, Wo);
    cudaEventRecord(evJoin, s1);

    // Main chain.
    prep_enc_kernel<<<BSH/256, 256>>>(enc, cov, wcov);
    qc_gemm_kernel<<<144, 256>>>(enc_p, Wc, a2_p, dec, Wq, bq, a1_p);
    scores_softmax_kernel<<<dim3(16, 8), 512>>>(v, align);
    c_splitk_kernel<<<dim3(8, 8, 4), 256>>>(align);
    out_splitk_c_kernel<<<dim3(8, 8, 2), 256>>>(Wo);

    // Join and final reduce (+bias).
    cudaStreamWaitEvent(0, evJoin, 0);
    out_reduce_kernel<<<TBH/1024, 256>>>(attn_h, bo);
}